// round 2
// baseline (speedup 1.0000x reference)
#include <cuda_runtime.h>
#include <math.h>

#define NB 16
#define NT 500
#define NH 100
#define HOP 64
#define NS (NT*HOP)

// scratch (no allocs allowed)
static __device__ float g_w [NB*NT*NH];   // [b][t][h] per-sample radian increment
static __device__ float g_la[NB*NT*NH];   // [b][t][h] loudness * masked amp
static __device__ float g_wT[NB*NH*NT];   // [b][h][t] transposed w for the scan
static __device__ float g_G [NB*(NT+1)*NH]; // [b][t][h] frame-prefix phase G(t), t=0..500

// ---------------- Kernel 1: per-(b,t,h) prep ----------------
__global__ void k_prep(const float* __restrict__ f0, const float* __restrict__ loud,
                       const float* __restrict__ amps, const float* __restrict__ stretch)
{
    int idx = blockIdx.x * blockDim.x + threadIdx.x;
    if (idx >= NB*NT*NH) return;
    int h  = idx % NH;
    int bt = idx / NH;

    float e = __fadd_rn(1.0f, stretch[bt]);            // 1 + harm_stretch (f32)
    // h^(e): correctly-rounded f32 via double exp/log (matches libm/libdevice powf to ~1 ulp)
    double hd = (double)(h + 1);
    float harm = (float)exp(log(hd) * (double)e);
    harm = __fmul_rn(harm, f0[bt]);                    // instantaneous freq (Hz)

    const float CW = (float)(6.283185307179586476925286766559 / 44100.0);
    float w = __fmul_rn(harm, CW);                     // rad/sample
    float a = (harm > 22050.0f) ? 0.0f : amps[idx];    // nyquist mask
    float la = __fmul_rn(loud[bt], a);                 // l * a (both constant within frame)

    g_w [idx] = w;
    g_la[idx] = la;
    int b = bt / NT;
    int t = bt - b * NT;
    g_wT[(b*NH + h)*NT + t] = w;
}

// ---------------- Kernel 2: per-(b,h) frame-level associative scan ----------------
// Replicates jax.lax.associative_scan rounding: prefix of t frames = left-fold
// (msb->lsb of t) of balanced-tree sums of aligned power-of-2 blocks of y_t = 64*w_t.
__global__ void k_scan()
{
    __shared__ float tr[994];       // tree levels 0..8 packed
    int c   = blockIdx.x;           // chain = b*NH + h
    int tid = threadIdx.x;          // 64 threads

    const float* wt = g_wT + (size_t)c * NT;
    for (int t = tid; t < NT; t += 64)
        tr[t] = __fmul_rn(64.0f, wt[t]);              // exact (power-of-2 scale)
    __syncthreads();

    const int OFF[9] = {0,500,750,875,937,968,983,990,993};
    const int LEN[9] = {500,250,125, 62, 31, 15,  7,  3,  1};
#pragma unroll
    for (int L = 1; L < 9; L++) {
        int po = OFF[L-1], o = OFF[L], n = LEN[L];
        for (int k = tid; k < n; k += 64)
            tr[o + k] = __fadd_rn(tr[po + 2*k], tr[po + 2*k + 1]);
        __syncthreads();
    }

    int b = c / NH;
    int h = c - b * NH;
    size_t gbase = ((size_t)b * (NT+1)) * NH + h;
    if (tid == 0) g_G[gbase] = 0.0f;                  // G(0)

    for (int t = tid + 1; t <= NT; t += 64) {
        float G = 0.0f; bool first = true; int pos = 0;
#pragma unroll
        for (int i = 8; i >= 0; i--) {
            if ((t >> i) & 1) {
                float v = tr[OFF[i] + (pos >> i)];
                G = first ? v : __fadd_rn(G, v);
                first = false;
                pos += (1 << i);
            }
        }
        g_G[gbase + (size_t)t * NH] = G;
    }
}

// ---------------- Kernel 3: per-(b,t) frame, thread j = sample ----------------
__global__ void k_gen(float* __restrict__ out)
{
    __shared__ float wS[NH], laS[NH], gS[2*NH];       // G(t) and G(t+1) rows are adjacent
    int bt = blockIdx.x;                              // b*NT + t
    int b  = bt / NT;
    int t  = bt - b * NT;
    int j  = threadIdx.x;                             // 0..63

    int    base  = bt * NH;
    size_t gbase = ((size_t)b * (NT+1) + t) * NH;
    for (int k = j; k < NH;   k += 64) { wS[k] = g_w[base + k]; laS[k] = g_la[base + k]; }
    for (int k = j; k < 2*NH; k += 64) { gS[k] = g_G[gbase + k]; }
    __syncthreads();

    int jm = j + 1;
    // fold weights: 2^i * w products are exact inside the fused FMA
    float b5 = (float)(jm & 32), b4 = (float)(jm & 16), b3 = (float)(jm & 8);
    float b2 = (float)(jm & 4),  b1 = (float)(jm & 2),  b0 = (float)(jm & 1);
    const float* gp = (jm == 64) ? (gS + NH) : gS;    // j=63 -> phase = G(t+1) exactly

    const float TWO_PI_F = 6.28318530717958647692f;   // fp32(2*pi) = 0x40C90FDB
    const float INV2PI   = 1.0f / 6.28318530717958647692f;
    const float MAGIC    = 12582912.0f;               // 1.5 * 2^23 round-to-int trick

    float a0 = 0.f, a1 = 0.f, a2 = 0.f, a3 = 0.f;
#pragma unroll 4
    for (int h = 0; h < NH; h += 4) {
#pragma unroll
        for (int u = 0; u < 4; u++) {
            int hh = h + u;
            float w = wS[hh];
            float p = gp[hh];
            p = __fmaf_rn(b5, w, p);                  // msb->lsb fold, bit-exact vs reference
            p = __fmaf_rn(b4, w, p);
            p = __fmaf_rn(b3, w, p);
            p = __fmaf_rn(b2, w, p);
            p = __fmaf_rn(b1, w, p);
            p = __fmaf_rn(b0, w, p);
            float q = __fadd_rn(__fmaf_rn(p, INV2PI, MAGIC), -MAGIC);  // ~round(p/2pi)
            float r = __fmaf_rn(q, -TWO_PI_F, p);     // exact-product FMA: <=1 ulp of fmodf
            float s = __sinf(r);
            float v = __fmaf_rn(laS[hh], s, 0.0f);
            if      (u == 0) a0 = __fadd_rn(a0, v);
            else if (u == 1) a1 = __fadd_rn(a1, v);
            else if (u == 2) a2 = __fadd_rn(a2, v);
            else             a3 = __fadd_rn(a3, v);
        }
    }
    float acc = __fadd_rn(__fadd_rn(a0, a1), __fadd_rn(a2, a3));
    out[(size_t)b * NS + t * HOP + j] = acc / 100.0f;
}

extern "C" void kernel_launch(void* const* d_in, const int* in_sizes, int n_in,
                              void* d_out, int out_size)
{
    const float* f0      = (const float*)d_in[0];
    const float* loud    = (const float*)d_in[1];
    const float* amps    = (const float*)d_in[2];
    const float* stretch = (const float*)d_in[3];
    float* out = (float*)d_out;

    k_prep<<<(NB*NT*NH + 255) / 256, 256>>>(f0, loud, amps, stretch);
    k_scan<<<NB*NH, 64>>>();
    k_gen<<<NB*NT, 64>>>(out);
}

// round 6
// speedup vs baseline: 1.6220x; 1.6220x over previous
#include <cuda_runtime.h>
#include <math.h>

#define NB 16
#define NT 500
#define NH 100
#define HOP 64
#define NS (NT*HOP)

// scratch (no allocs allowed)
static __device__ float  g_w [NB*NT*NH];     // [b][t][h] per-sample radian increment
static __device__ float  g_la[NB*NT*NH];     // [b][t][h] loudness * masked amp
static __device__ float  g_wT[NB*NH*NT];     // [b][h][t] transposed w for the scan
static __device__ float  g_G [NB*(NT+1)*NH]; // [b][t][h] frame-prefix phase G(t)
static __device__ double g_log2h[NH];        // log2(1..100), correctly rounded double

// ---------------- Kernel 0: tiny log2 table (100 doubles, ~0 cost) ----------------
__global__ void k_table()
{
    int h = threadIdx.x;
    if (h < NH) g_log2h[h] = log2((double)(h + 1));
}

// ---------------- Kernel 1: per-(b,t,h) prep with cheap double exp2 ----------------
__global__ void k_prep(const float* __restrict__ f0, const float* __restrict__ loud,
                       const float* __restrict__ amps, const float* __restrict__ stretch)
{
    int idx = blockIdx.x * blockDim.x + threadIdx.x;
    if (idx >= NB*NT*NH) return;
    int h  = idx % NH;
    int bt = idx / NH;

    float e = __fadd_rn(1.0f, stretch[bt]);            // 1 + harm_stretch (f32)

    // harm = h^(e) = 2^(e * log2(h)), computed to ~2^-40 rel in double, then f32-rounded.
    // y in [0, 13.33]; n = rint(y); r = y - n in [-0.5, 0.5].
    double y = (double)e * g_log2h[h];
    int    ni = __double2int_rn(y);
    double r  = y - (double)ni;                        // exact
    // degree-11 Taylor of 2^r = exp(r*ln2); remainder ~2^-47 rel on [-0.5,0.5]
    double z;
    z = 4.445538271870811e-10;
    z = fma(z, r, 7.054911620801121e-9);
    z = fma(z, r, 1.0178086009239699e-7);
    z = fma(z, r, 1.3215486790144305e-6);
    z = fma(z, r, 1.5252733804059838e-5);
    z = fma(z, r, 1.5403530393381608e-4);
    z = fma(z, r, 1.3333558146428443e-3);
    z = fma(z, r, 9.618129107628477e-3);
    z = fma(z, r, 5.550410866482158e-2);
    z = fma(z, r, 2.402265069591007e-1);
    z = fma(z, r, 6.931471805599453e-1);
    z = fma(z, r, 1.0);
    // scale by 2^ni via exponent-field add (n in [0,13], z in (0.70,1.42) -> safe)
    z = __longlong_as_double(__double_as_longlong(z) + ((long long)ni << 52));

    float harm = __fmul_rn((float)z, f0[bt]);          // instantaneous freq (Hz)

    const float CW = (float)(6.283185307179586476925286766559 / 44100.0);
    float w = __fmul_rn(harm, CW);                     // rad/sample
    float a = (harm > 22050.0f) ? 0.0f : amps[idx];    // nyquist mask
    float la = __fmul_rn(loud[bt], a);                 // l * a (constant within frame)

    g_w [idx] = w;
    g_la[idx] = la;
    int b = bt / NT;
    int t = bt - b * NT;
    g_wT[(b*NH + h)*NT + t] = w;
}

// ---------------- Kernel 2: per-(b,h) frame-level associative scan ----------------
// Replicates jax.lax.associative_scan rounding: prefix of t frames = left-fold
// (msb->lsb of t) of balanced-tree sums of aligned power-of-2 blocks of y_t = 64*w_t.
__global__ void k_scan()
{
    __shared__ float tr[994];       // tree levels 0..8 packed
    int c   = blockIdx.x;           // chain = b*NH + h
    int tid = threadIdx.x;          // 64 threads

    const float* wt = g_wT + (size_t)c * NT;
    for (int t = tid; t < NT; t += 64)
        tr[t] = __fmul_rn(64.0f, wt[t]);              // exact (power-of-2 scale)
    __syncthreads();

    const int OFF[9] = {0,500,750,875,937,968,983,990,993};
    const int LEN[9] = {500,250,125, 62, 31, 15,  7,  3,  1};
#pragma unroll
    for (int L = 1; L < 9; L++) {
        int po = OFF[L-1], o = OFF[L], n = LEN[L];
        for (int k = tid; k < n; k += 64)
            tr[o + k] = __fadd_rn(tr[po + 2*k], tr[po + 2*k + 1]);
        __syncthreads();
    }

    int b = c / NH;
    int h = c - b * NH;
    size_t gbase = ((size_t)b * (NT+1)) * NH + h;
    if (tid == 0) g_G[gbase] = 0.0f;                  // G(0)

    for (int t = tid + 1; t <= NT; t += 64) {
        float G = 0.0f; bool first = true; int pos = 0;
#pragma unroll
        for (int i = 8; i >= 0; i--) {
            if ((t >> i) & 1) {
                float v = tr[OFF[i] + (pos >> i)];
                G = first ? v : __fadd_rn(G, v);
                first = false;
                pos += (1 << i);
            }
        }
        g_G[gbase + (size_t)t * NH] = G;
    }
}

// ---------------- Kernel 3: per-(b,t) frame, thread j = sample ----------------
__global__ void k_gen(float* __restrict__ out)
{
    __shared__ float wS[NH], laS[NH], gS[2*NH];       // G(t) and G(t+1) rows are adjacent
    int bt = blockIdx.x;                              // b*NT + t
    int b  = bt / NT;
    int t  = bt - b * NT;
    int j  = threadIdx.x;                             // 0..63

    int    base  = bt * NH;
    size_t gbase = ((size_t)b * (NT+1) + t) * NH;
    for (int k = j; k < NH;   k += 64) { wS[k] = g_w[base + k]; laS[k] = g_la[base + k]; }
    for (int k = j; k < 2*NH; k += 64) { gS[k] = g_G[gbase + k]; }
    __syncthreads();

    int jm = j + 1;
    // fold weights: 2^i * w products are exact inside the fused FMA
    float b5 = (float)(jm & 32), b4 = (float)(jm & 16), b3 = (float)(jm & 8);
    float b2 = (float)(jm & 4),  b1 = (float)(jm & 2),  b0 = (float)(jm & 1);
    const float* gp = (jm == 64) ? (gS + NH) : gS;    // j=63 -> phase = G(t+1) exactly

    const float TWO_PI_F = 6.28318530717958647692f;   // fp32(2*pi) = 0x40C90FDB
    const float INV2PI   = 1.0f / 6.28318530717958647692f;
    const float MAGIC    = 12582912.0f;               // 1.5 * 2^23 round-to-int trick

    float a0 = 0.f, a1 = 0.f, a2 = 0.f, a3 = 0.f;
#pragma unroll 4
    for (int h = 0; h < NH; h += 4) {
#pragma unroll
        for (int u = 0; u < 4; u++) {
            int hh = h + u;
            float w = wS[hh];
            float p = gp[hh];
            p = __fmaf_rn(b5, w, p);                  // msb->lsb fold, bit-exact vs reference
            p = __fmaf_rn(b4, w, p);
            p = __fmaf_rn(b3, w, p);
            p = __fmaf_rn(b2, w, p);
            p = __fmaf_rn(b1, w, p);
            p = __fmaf_rn(b0, w, p);
            float q = __fadd_rn(__fmaf_rn(p, INV2PI, MAGIC), -MAGIC);  // ~round(p/2pi)
            float r = __fmaf_rn(q, -TWO_PI_F, p);     // exact-product FMA: <=1 ulp of fmodf
            float s = __sinf(r);
            float v = __fmaf_rn(laS[hh], s, 0.0f);
            if      (u == 0) a0 = __fadd_rn(a0, v);
            else if (u == 1) a1 = __fadd_rn(a1, v);
            else if (u == 2) a2 = __fadd_rn(a2, v);
            else             a3 = __fadd_rn(a3, v);
        }
    }
    float acc = __fadd_rn(__fadd_rn(a0, a1), __fadd_rn(a2, a3));
    out[(size_t)b * NS + t * HOP + j] = acc / 100.0f;
}

extern "C" void kernel_launch(void* const* d_in, const int* in_sizes, int n_in,
                              void* d_out, int out_size)
{
    const float* f0      = (const float*)d_in[0];
    const float* loud    = (const float*)d_in[1];
    const float* amps    = (const float*)d_in[2];
    const float* stretch = (const float*)d_in[3];
    float* out = (float*)d_out;

    k_table<<<1, 128>>>();
    k_prep<<<(NB*NT*NH + 255) / 256, 256>>>(f0, loud, amps, stretch);
    k_scan<<<NB*NH, 64>>>();
    k_gen<<<NB*NT, 64>>>(out);
}

// round 7
// speedup vs baseline: 1.8133x; 1.1179x over previous
#include <cuda_runtime.h>
#include <math.h>

#define NB 16
#define NT 500
#define NH 100
#define HOP 64
#define NS (NT*HOP)

// scratch (no allocs allowed)
static __device__ float  g_w [NB*NT*NH];     // [b][t][h] per-sample radian increment
static __device__ float  g_la[NB*NT*NH];     // [b][t][h] loudness * masked amp
static __device__ float  g_wT[NB*NH*NT];     // [b][h][t] transposed w for the scan
static __device__ float  g_G [NB*(NT+1)*NH]; // [b][t][h] frame-prefix phase G(t)
static __device__ double g_L64[NH];          // 64*log2(1..100), double
static __device__ double g_T[64];            // 2^(k/64), k=0..63, double

// ---------------- Kernel 0: tiny tables (~0 cost) ----------------
__global__ void k_table()
{
    int h = threadIdx.x;
    if (h < NH) g_L64[h] = 64.0 * log2((double)(h + 1));
    if (h < 64) g_T[h]   = exp2((double)h * 0.015625);
}

// ---------------- Kernel 1: per-(b,t,h) prep, 8 FP64 ops via table+deg4 ----------------
__global__ void k_prep(const float* __restrict__ f0, const float* __restrict__ loud,
                       const float* __restrict__ amps, const float* __restrict__ stretch)
{
    int idx = blockIdx.x * blockDim.x + threadIdx.x;
    if (idx >= NB*NT*NH) return;
    int h  = idx % NH;
    int bt = idx / NH;

    float e = __fadd_rn(1.0f, stretch[bt]);            // 1 + harm_stretch (f32)

    // harm = h^e = 2^(e*log2 h).  y64 = 64*y;  n64 = rint(y64);  r2 = (y64-n64)/64.
    // 2^y = 2^(n64>>6) * T[n64&63] * 2^r2, 2^r2 by degree-4 Taylor (rem ~2^-44.6).
    double y64 = (double)e * g_L64[h];                 // DMUL
    int    n64 = __double2int_rn(y64);                 // >= 0 always
    double d   = y64 - (double)n64;                    // exact (|d|<=0.5)
    double r2  = d * 0.015625;                         // exact (2^-6 scale)
    double z;
    z = 9.618129107628477e-3;                          // ln2^4/24
    z = fma(z, r2, 5.550410866482158e-2);              // ln2^3/6
    z = fma(z, r2, 2.402265069591007e-1);              // ln2^2/2
    z = fma(z, r2, 6.931471805599453e-1);              // ln2
    z = fma(z, r2, 1.0);
    z = z * g_T[n64 & 63];                             // DMUL
    z = __longlong_as_double(__double_as_longlong(z) + ((long long)(n64 >> 6) << 52));

    float harm = __fmul_rn((float)z, f0[bt]);          // instantaneous freq (Hz)

    const float CW = (float)(6.283185307179586476925286766559 / 44100.0);
    float w = __fmul_rn(harm, CW);                     // rad/sample
    float a = (harm > 22050.0f) ? 0.0f : amps[idx];    // nyquist mask
    float la = __fmul_rn(loud[bt], a);                 // l * a (constant within frame)

    g_w [idx] = w;
    g_la[idx] = la;
    int b = bt / NT;
    int t = bt - b * NT;
    g_wT[(b*NH + h)*NT + t] = w;
}

// ---------------- Kernel 2: per-(b,h) frame-level associative scan ----------------
// Replicates jax.lax.associative_scan rounding: prefix of t frames = left-fold
// (msb->lsb of t) of balanced-tree sums of aligned power-of-2 blocks of y_t = 64*w_t.
__global__ void k_scan()
{
    __shared__ float tr[994];       // tree levels 0..8 packed
    int c   = blockIdx.x;           // chain = b*NH + h
    int tid = threadIdx.x;          // 64 threads

    const float* wt = g_wT + (size_t)c * NT;
    for (int t = tid; t < NT; t += 64)
        tr[t] = __fmul_rn(64.0f, wt[t]);              // exact (power-of-2 scale)
    __syncthreads();

    const int OFF[9] = {0,500,750,875,937,968,983,990,993};
    const int LEN[9] = {500,250,125, 62, 31, 15,  7,  3,  1};
#pragma unroll
    for (int L = 1; L < 9; L++) {
        int po = OFF[L-1], o = OFF[L], n = LEN[L];
        for (int k = tid; k < n; k += 64)
            tr[o + k] = __fadd_rn(tr[po + 2*k], tr[po + 2*k + 1]);
        __syncthreads();
    }

    int b = c / NH;
    int h = c - b * NH;
    size_t gbase = ((size_t)b * (NT+1)) * NH + h;
    if (tid == 0) g_G[gbase] = 0.0f;                  // G(0)

    for (int t = tid + 1; t <= NT; t += 64) {
        float G = 0.0f; bool first = true; int pos = 0;
#pragma unroll
        for (int i = 8; i >= 0; i--) {
            if ((t >> i) & 1) {
                float v = tr[OFF[i] + (pos >> i)];
                G = first ? v : __fadd_rn(G, v);
                first = false;
                pos += (1 << i);
            }
        }
        g_G[gbase + (size_t)t * NH] = G;
    }
}

// ---------------- Kernel 3: per-(b,t) frame, thread j = sample ----------------
__global__ void k_gen(float* __restrict__ out)
{
    __shared__ __align__(16) float wS[NH];
    __shared__ __align__(16) float laS[NH];
    __shared__ __align__(16) float gS[2*NH];          // G(t) and G(t+1) rows adjacent
    int bt = blockIdx.x;                              // b*NT + t
    int b  = bt / NT;
    int t  = bt - b * NT;
    int j  = threadIdx.x;                             // 0..63

    int    base  = bt * NH;
    size_t gbase = ((size_t)b * (NT+1) + t) * NH;
    // vectorized fills (all global offsets are multiples of 400B -> 16B aligned)
    {
        const float4* gw  = reinterpret_cast<const float4*>(g_w  + base);
        const float4* gla = reinterpret_cast<const float4*>(g_la + base);
        const float4* gg  = reinterpret_cast<const float4*>(g_G  + gbase);
        float4* w4  = reinterpret_cast<float4*>(wS);
        float4* la4 = reinterpret_cast<float4*>(laS);
        float4* g4  = reinterpret_cast<float4*>(gS);
        for (int k = j; k < NH/4;   k += 64) { w4[k] = gw[k]; la4[k] = gla[k]; }
        for (int k = j; k < 2*NH/4; k += 64) { g4[k] = gg[k]; }
    }
    __syncthreads();

    int jm = j + 1;
    // fold weights: 2^i * w products are exact inside the fused FMA
    float b5 = (float)(jm & 32), b4 = (float)(jm & 16), b3 = (float)(jm & 8);
    float b2 = (float)(jm & 4),  b1 = (float)(jm & 2),  b0 = (float)(jm & 1);
    const float* gp = (jm == 64) ? (gS + NH) : gS;    // j=63 -> phase = G(t+1) exactly

    const float TWO_PI_F = 6.28318530717958647692f;   // fp32(2*pi) = 0x40C90FDB
    const float INV2PI   = 1.0f / 6.28318530717958647692f;
    const float MAGIC    = 12582912.0f;               // 1.5 * 2^23 round-to-int trick

    const float4* w4p  = reinterpret_cast<const float4*>(wS);
    const float4* la4p = reinterpret_cast<const float4*>(laS);
    const float4* g4p  = reinterpret_cast<const float4*>(gp);

    float a0 = 0.f, a1 = 0.f, a2 = 0.f, a3 = 0.f;
#pragma unroll 5
    for (int h4 = 0; h4 < NH/4; h4++) {
        float4 w4  = w4p[h4];
        float4 la4 = la4p[h4];
        float4 g4  = g4p[h4];
#pragma unroll
        for (int u = 0; u < 4; u++) {
            float w  = (u == 0) ? w4.x  : (u == 1) ? w4.y  : (u == 2) ? w4.z  : w4.w;
            float la = (u == 0) ? la4.x : (u == 1) ? la4.y : (u == 2) ? la4.z : la4.w;
            float p  = (u == 0) ? g4.x  : (u == 1) ? g4.y  : (u == 2) ? g4.z  : g4.w;
            p = __fmaf_rn(b5, w, p);                  // msb->lsb fold, bit-exact vs reference
            p = __fmaf_rn(b4, w, p);
            p = __fmaf_rn(b3, w, p);
            p = __fmaf_rn(b2, w, p);
            p = __fmaf_rn(b1, w, p);
            p = __fmaf_rn(b0, w, p);
            float q = __fadd_rn(__fmaf_rn(p, INV2PI, MAGIC), -MAGIC);  // ~round(p/2pi)
            float r = __fmaf_rn(q, -TWO_PI_F, p);     // exact-product FMA: <=1 ulp of fmodf
            float s = __sinf(r);
            if      (u == 0) a0 = __fmaf_rn(la, s, a0);
            else if (u == 1) a1 = __fmaf_rn(la, s, a1);
            else if (u == 2) a2 = __fmaf_rn(la, s, a2);
            else             a3 = __fmaf_rn(la, s, a3);
        }
    }
    float acc = __fadd_rn(__fadd_rn(a0, a1), __fadd_rn(a2, a3));
    out[(size_t)b * NS + t * HOP + j] = acc / 100.0f;
}

extern "C" void kernel_launch(void* const* d_in, const int* in_sizes, int n_in,
                              void* d_out, int out_size)
{
    const float* f0      = (const float*)d_in[0];
    const float* loud    = (const float*)d_in[1];
    const float* amps    = (const float*)d_in[2];
    const float* stretch = (const float*)d_in[3];
    float* out = (float*)d_out;

    k_table<<<1, 128>>>();
    k_prep<<<(NB*NT*NH + 255) / 256, 256>>>(f0, loud, amps, stretch);
    k_scan<<<NB*NH, 64>>>();
    k_gen<<<NB*NT, 64>>>(out);
}

// round 8
// speedup vs baseline: 1.9504x; 1.0756x over previous
#include <cuda_runtime.h>
#include <math.h>

#define NB 16
#define NT 500
#define NH 100
#define HOP 64
#define NS (NT*HOP)

// scratch (no allocs allowed)
static __device__ float  g_w [NB*NT*NH];     // [b][t][h] per-sample radian increment
static __device__ float  g_la[NB*NT*NH];     // [b][t][h] loudness * masked amp
static __device__ float  g_wT[NB*NH*NT];     // [b][h][t] transposed w for the scan
static __device__ float  g_G [NB*(NT+1)*NH]; // [b][t][h] frame-prefix phase G(t)
static __device__ double g_L64[NH];          // 64*log2(1..100), double
static __device__ double g_T[64];            // 2^(k/64), k=0..63, double

// ---- packed f32x2 helpers (FFMA2/FADD2 only reachable via PTX) ----
__device__ __forceinline__ unsigned long long pk2(float lo, float hi) {
    unsigned long long r; asm("mov.b64 %0, {%1,%2};" : "=l"(r) : "f"(lo), "f"(hi)); return r;
}
__device__ __forceinline__ void upk2(unsigned long long v, float& lo, float& hi) {
    asm("mov.b64 {%0,%1}, %2;" : "=f"(lo), "=f"(hi) : "l"(v));
}
__device__ __forceinline__ unsigned long long fma2(unsigned long long a,
                                                   unsigned long long b,
                                                   unsigned long long c) {
    unsigned long long d;
    asm("fma.rn.f32x2 %0, %1, %2, %3;" : "=l"(d) : "l"(a), "l"(b), "l"(c));
    return d;
}
__device__ __forceinline__ unsigned long long add2(unsigned long long a,
                                                   unsigned long long b) {
    unsigned long long d;
    asm("add.rn.f32x2 %0, %1, %2;" : "=l"(d) : "l"(a), "l"(b));
    return d;
}

// ---------------- Kernel 0: tiny tables (~0 cost) ----------------
__global__ void k_table()
{
    int h = threadIdx.x;
    if (h < NH) g_L64[h] = 64.0 * log2((double)(h + 1));
    if (h < 64) g_T[h]   = exp2((double)h * 0.015625);
}

// ---------------- Kernel 1: per-(b,t,h) prep, 8 FP64 ops via table+deg4 ----------------
__global__ void k_prep(const float* __restrict__ f0, const float* __restrict__ loud,
                       const float* __restrict__ amps, const float* __restrict__ stretch)
{
    int idx = blockIdx.x * blockDim.x + threadIdx.x;
    if (idx >= NB*NT*NH) return;
    int h  = idx % NH;
    int bt = idx / NH;

    float e = __fadd_rn(1.0f, stretch[bt]);            // 1 + harm_stretch (f32)

    // harm = h^e = 2^(e*log2 h).  y64 = 64*y;  n64 = rint(y64);  r2 = (y64-n64)/64.
    double y64 = (double)e * g_L64[h];
    int    n64 = __double2int_rn(y64);
    double d   = y64 - (double)n64;                    // exact (|d|<=0.5)
    double r2  = d * 0.015625;                         // exact (2^-6 scale)
    double z;
    z = 9.618129107628477e-3;
    z = fma(z, r2, 5.550410866482158e-2);
    z = fma(z, r2, 2.402265069591007e-1);
    z = fma(z, r2, 6.931471805599453e-1);
    z = fma(z, r2, 1.0);
    z = z * g_T[n64 & 63];
    z = __longlong_as_double(__double_as_longlong(z) + ((long long)(n64 >> 6) << 52));

    float harm = __fmul_rn((float)z, f0[bt]);          // instantaneous freq (Hz)

    const float CW = (float)(6.283185307179586476925286766559 / 44100.0);
    float w = __fmul_rn(harm, CW);                     // rad/sample
    float a = (harm > 22050.0f) ? 0.0f : amps[idx];    // nyquist mask
    float la = __fmul_rn(loud[bt], a);                 // l * a (constant within frame)

    g_w [idx] = w;
    g_la[idx] = la;
    int b = bt / NT;
    int t = bt - b * NT;
    g_wT[(b*NH + h)*NT + t] = w;
}

// ---------------- Kernel 2: per-(b,h) frame-level associative scan ----------------
__global__ void k_scan()
{
    __shared__ float tr[994];       // tree levels 0..8 packed
    int c   = blockIdx.x;           // chain = b*NH + h
    int tid = threadIdx.x;          // 64 threads

    const float* wt = g_wT + (size_t)c * NT;
    for (int t = tid; t < NT; t += 64)
        tr[t] = __fmul_rn(64.0f, wt[t]);              // exact (power-of-2 scale)
    __syncthreads();

    const int OFF[9] = {0,500,750,875,937,968,983,990,993};
    const int LEN[9] = {500,250,125, 62, 31, 15,  7,  3,  1};
#pragma unroll
    for (int L = 1; L < 9; L++) {
        int po = OFF[L-1], o = OFF[L], n = LEN[L];
        for (int k = tid; k < n; k += 64)
            tr[o + k] = __fadd_rn(tr[po + 2*k], tr[po + 2*k + 1]);
        __syncthreads();
    }

    int b = c / NH;
    int h = c - b * NH;
    size_t gbase = ((size_t)b * (NT+1)) * NH + h;
    if (tid == 0) g_G[gbase] = 0.0f;                  // G(0)

    for (int t = tid + 1; t <= NT; t += 64) {
        float G = 0.0f; bool first = true; int pos = 0;
#pragma unroll
        for (int i = 8; i >= 0; i--) {
            if ((t >> i) & 1) {
                float v = tr[OFF[i] + (pos >> i)];
                G = first ? v : __fadd_rn(G, v);
                first = false;
                pos += (1 << i);
            }
        }
        g_G[gbase + (size_t)t * NH] = G;
    }
}

// ---------------- Kernel 3: per-(b,t) frame, thread j = sample, f32x2 packed ----------------
__global__ void k_gen(float* __restrict__ out)
{
    __shared__ __align__(16) float wS[NH];
    __shared__ __align__(16) float laS[NH];
    __shared__ __align__(16) float gS[2*NH];          // G(t) and G(t+1) rows adjacent
    int bt = blockIdx.x;                              // b*NT + t
    int b  = bt / NT;
    int t  = bt - b * NT;
    int j  = threadIdx.x;                             // 0..63

    int    base  = bt * NH;
    size_t gbase = ((size_t)b * (NT+1) + t) * NH;
    {
        const float4* gw  = reinterpret_cast<const float4*>(g_w  + base);
        const float4* gla = reinterpret_cast<const float4*>(g_la + base);
        const float4* gg  = reinterpret_cast<const float4*>(g_G  + gbase);
        float4* w4  = reinterpret_cast<float4*>(wS);
        float4* la4 = reinterpret_cast<float4*>(laS);
        float4* g4  = reinterpret_cast<float4*>(gS);
        for (int k = j; k < NH/4;   k += 64) { w4[k] = gw[k]; la4[k] = gla[k]; }
        for (int k = j; k < 2*NH/4; k += 64) { g4[k] = gg[k]; }
    }
    __syncthreads();

    int jm = j + 1;
    // packed fold weights (value broadcast to both lanes); 2^i*w exact inside the FMA
    unsigned long long B5 = pk2((float)(jm & 32), (float)(jm & 32));
    unsigned long long B4 = pk2((float)(jm & 16), (float)(jm & 16));
    unsigned long long B3 = pk2((float)(jm & 8),  (float)(jm & 8));
    unsigned long long B2 = pk2((float)(jm & 4),  (float)(jm & 4));
    unsigned long long B1 = pk2((float)(jm & 2),  (float)(jm & 2));
    unsigned long long B0 = pk2((float)(jm & 1),  (float)(jm & 1));
    const float* gp = (jm == 64) ? (gS + NH) : gS;    // j=63 -> phase = G(t+1) exactly

    const float TWO_PI_F = 6.28318530717958647692f;   // fp32(2*pi) = 0x40C90FDB
    const float INV2PI   = 1.0f / 6.28318530717958647692f;
    const float MAGIC    = 12582912.0f;               // 1.5 * 2^23 round-to-int trick
    unsigned long long INV2   = pk2(INV2PI,  INV2PI);
    unsigned long long MAG2   = pk2(MAGIC,   MAGIC);
    unsigned long long NMAG2  = pk2(-MAGIC, -MAGIC);
    unsigned long long N2PI2  = pk2(-TWO_PI_F, -TWO_PI_F);

    const unsigned long long* w2p = reinterpret_cast<const unsigned long long*>(wS);
    const unsigned long long* g2p = reinterpret_cast<const unsigned long long*>(gp);
    const float2*             l2p = reinterpret_cast<const float2*>(laS);

    float a0 = 0.f, a1 = 0.f, a2 = 0.f, a3 = 0.f;
#pragma unroll 5
    for (int k = 0; k < NH/4; k++) {                  // 2 packed pairs per iter
        // pair A: harmonics 4k, 4k+1
        {
            unsigned long long w2 = w2p[2*k], p2 = g2p[2*k];
            float2 l2 = l2p[2*k];
            p2 = fma2(B5, w2, p2);                    // msb->lsb fold, bit-exact per lane
            p2 = fma2(B4, w2, p2);
            p2 = fma2(B3, w2, p2);
            p2 = fma2(B2, w2, p2);
            p2 = fma2(B1, w2, p2);
            p2 = fma2(B0, w2, p2);
            unsigned long long q2 = add2(fma2(p2, INV2, MAG2), NMAG2);  // ~round(p/2pi)
            unsigned long long r2 = fma2(q2, N2PI2, p2);                // <=1 ulp of fmodf
            float r0, r1; upk2(r2, r0, r1);
            a0 = __fmaf_rn(l2.x, __sinf(r0), a0);
            a1 = __fmaf_rn(l2.y, __sinf(r1), a1);
        }
        // pair B: harmonics 4k+2, 4k+3
        {
            unsigned long long w2 = w2p[2*k+1], p2 = g2p[2*k+1];
            float2 l2 = l2p[2*k+1];
            p2 = fma2(B5, w2, p2);
            p2 = fma2(B4, w2, p2);
            p2 = fma2(B3, w2, p2);
            p2 = fma2(B2, w2, p2);
            p2 = fma2(B1, w2, p2);
            p2 = fma2(B0, w2, p2);
            unsigned long long q2 = add2(fma2(p2, INV2, MAG2), NMAG2);
            unsigned long long r2 = fma2(q2, N2PI2, p2);
            float r0, r1; upk2(r2, r0, r1);
            a2 = __fmaf_rn(l2.x, __sinf(r0), a2);
            a3 = __fmaf_rn(l2.y, __sinf(r1), a3);
        }
    }
    float acc = __fadd_rn(__fadd_rn(a0, a1), __fadd_rn(a2, a3));
    out[(size_t)b * NS + t * HOP + j] = acc / 100.0f;
}

extern "C" void kernel_launch(void* const* d_in, const int* in_sizes, int n_in,
                              void* d_out, int out_size)
{
    const float* f0      = (const float*)d_in[0];
    const float* loud    = (const float*)d_in[1];
    const float* amps    = (const float*)d_in[2];
    const float* stretch = (const float*)d_in[3];
    float* out = (float*)d_out;

    k_table<<<1, 128>>>();
    k_prep<<<(NB*NT*NH + 255) / 256, 256>>>(f0, loud, amps, stretch);
    k_scan<<<NB*NH, 64>>>();
    k_gen<<<NB*NT, 64>>>(out);
}